// round 6
// baseline (speedup 1.0000x reference)
#include <cuda_runtime.h>
#include <cstdint>

#define THREADS 512
#define ROWS_PER_BLOCK 8

typedef unsigned long long ull;

// ---------------- shared memory layout (float indices) ----------------
#define SM_W1D  0            // [112][256]  w1 k-major, o duplicated-pairs, swizzled
#define SM_W2   28672        // [128][32]   w2 transposed
#define SM_PERC 32768        // [112][128]  perceive (rows 0..31 become new_state)
#define SM_HSH  47104        // [64][128]   hidden half-buffer, swizzled
#define SM_B1   55296
#define SM_B2   55424
#define SM_G    55456
#define SM_BETA 55488
#define SM_MU   55520
#define SM_RS   55648
#define SM_INV  55776
#define SM_TOTAL 55904       // 223,616 bytes

// packed f32x2 helpers
__device__ __forceinline__ void ffma2(ull& d, ull a, ull b) {
    asm("fma.rn.f32x2 %0, %1, %2, %0;" : "+l"(d) : "l"(a), "l"(b));
}
__device__ __forceinline__ ull bcast2(float v) {
    ull r;
    asm("mov.b64 %0, {%1, %1};" : "=l"(r) : "f"(v));
    return r;
}
__device__ __forceinline__ void unpack2(ull p, float& lo, float& hi) {
    asm("mov.b64 {%0, %1}, %2;" : "=f"(lo), "=f"(hi) : "l"(p));
}

extern __shared__ float smem[];

__global__ void __launch_bounds__(THREADS)
cellnn_kernel(const float* __restrict__ x,
              const float* __restrict__ w1,
              const float* __restrict__ b1,
              const float* __restrict__ w2,
              const float* __restrict__ b2,
              const float* __restrict__ gamma,
              const float* __restrict__ beta,
              float* __restrict__ out)
{
    char*  w1db = (char*)(smem + SM_W1D);
    float* w2s  = smem + SM_W2;
    float* perc = smem + SM_PERC;
    char*  hsb  = (char*)(smem + SM_HSH);
    float* b1s  = smem + SM_B1;
    float* b2s  = smem + SM_B2;
    float* gs   = smem + SM_G;
    float* bss  = smem + SM_BETA;
    float* mus  = smem + SM_MU;
    float* rss  = smem + SM_RS;
    float* invs = smem + SM_INV;

    const int tid  = threadIdx.x;
    const int lane = tid & 31;
    const int warp = tid >> 5;

    // ---- stage W1 as duplicated pairs: w1d[k][2o]=[2o+1]=w1[o][k], swizzled ----
    // swizzle: addr ^ ((addr>>6)&0xF0)  (k bits 0-3 -> byte bits 4-7)
    for (int i = tid; i < 128 * 112; i += THREADS) {
        int o = i / 112;
        int k = i - o * 112;
        float v = w1[i];                               // coalesced
        uint32_t a = (uint32_t)(k * 1024 + o * 8);
        a ^= (a >> 6) & 0xF0;
        *(float2*)(w1db + a) = make_float2(v, v);
    }
    // ---- stage W2 transposed: w2s[k][c] = w2[c][k] ----
    for (int i = tid; i < 128 * 32; i += THREADS) {
        int k = i >> 5, c = i & 31;
        w2s[i] = w2[c * 128 + k];
    }
    if (tid < 128) b1s[tid] = b1[tid];
    if (tid < 32) { b2s[tid] = b2[tid]; gs[tid] = gamma[tid]; bss[tid] = beta[tid]; }
    __syncthreads();

    const int row0 = blockIdx.x * ROWS_PER_BLOCK;
    const int bi   = row0 >> 7;
    const float* xb = x   + (size_t)bi * 32 * 128 * 128;
    float*       ob = out + (size_t)bi * 32 * 128 * 128;

    // GEMM1 half-mapping: 16 warps cover 128px x 64o; warp tile 32px x 16o
    const int g1_p0  = ((warp & 3) * 4 + (lane & 3)) * 8;      // 8 px
    const int g1_oh  = (warp >> 2) * 16 + (lane >> 2) * 2;     // 2 o within half
    // GEMM2 mapping: warp tile 32px x 8ch
    const int g2_p0  = g1_p0;
    const int g2_c   = (warp >> 2) * 8 + (lane >> 2);

    for (int r = 0; r < ROWS_PER_BLOCK; ++r) {
        const int y = (row0 & 127) + r;

        // ---- build perc[112][128] ----
        for (int i = tid; i < 32 * 128; i += THREADS) {
            int c = i >> 7, p = i & 127;
            perc[i] = xb[(c * 128 + y) * 128 + p];
        }
        for (int i = tid; i < 80 * 128; i += THREADS) {
            int kk = i >> 7, p = i & 127;
            int c  = kk >> 3, s = kk & 7;
            int idx = s + (s >= 4 ? 1 : 0);
            int ki  = idx / 3;
            int dy  = ki - 1;
            int dx  = idx - ki * 3 - 1;
            int yy  = y + dy, xx = p + dx;
            float v = 0.0f;
            if ((unsigned)yy < 128u && (unsigned)xx < 128u)
                v = xb[(c * 128 + yy) * 128 + xx];
            perc[(32 + kk) * 128 + p] = v;
        }
        __syncthreads();

        ull dacc[4] = {0ull, 0ull, 0ull, 0ull};

        #pragma unroll
        for (int h = 0; h < 2; ++h) {
            // ---- GEMM1 half h: hsh[64o][128px] = relu(W1[h] @ perc + b1) ----
            {
                ull acc[4][2];
                #pragma unroll
                for (int i = 0; i < 4; ++i) { acc[i][0] = 0ull; acc[i][1] = 0ull; }

                const char* pa = (const char*)perc + g1_p0 * 4;
                const uint32_t wbase = (uint32_t)(h * 512 + g1_oh * 8);
                #pragma unroll 8
                for (int k = 0; k < 112; ++k) {
                    ulonglong2 a01 = *(const ulonglong2*)(pa + k * 512);
                    ulonglong2 a23 = *(const ulonglong2*)(pa + k * 512 + 16);
                    uint32_t wa = (wbase + (uint32_t)(k * 1024));
                    wa ^= (wa >> 6) & 0xF0;
                    ulonglong2 wv = *(const ulonglong2*)(w1db + wa);
                    ffma2(acc[0][0], a01.x, wv.x);
                    ffma2(acc[1][0], a01.y, wv.x);
                    ffma2(acc[2][0], a23.x, wv.x);
                    ffma2(acc[3][0], a23.y, wv.x);
                    ffma2(acc[0][1], a01.x, wv.y);
                    ffma2(acc[1][1], a01.y, wv.y);
                    ffma2(acc[2][1], a23.x, wv.y);
                    ffma2(acc[3][1], a23.y, wv.y);
                }
                #pragma unroll
                for (int j = 0; j < 2; ++j) {
                    float bj = b1s[h * 64 + g1_oh + j];
                    float hv[8];
                    #pragma unroll
                    for (int i = 0; i < 4; ++i) {
                        float lo, hi; unpack2(acc[i][j], lo, hi);
                        hv[2 * i]     = fmaxf(lo + bj, 0.0f);
                        hv[2 * i + 1] = fmaxf(hi + bj, 0.0f);
                    }
                    uint32_t sa = (uint32_t)((g1_oh + j) * 512 + g1_p0 * 4);
                    sa ^= (sa >> 6) & 0x70;
                    *(float4*)(hsb + sa)        = make_float4(hv[0], hv[1], hv[2], hv[3]);
                    *(float4*)(hsb + (sa ^ 16)) = make_float4(hv[4], hv[5], hv[6], hv[7]);
                }
            }
            __syncthreads();

            // ---- GEMM2 half h: dacc += W2[:, h*64..] @ hsh ----
            {
                const float* pw2 = w2s + h * 64 * 32 + g2_c;
                #pragma unroll 8
                for (int k = 0; k < 64; ++k) {
                    ull wv = bcast2(pw2[k * 32]);
                    uint32_t ba = (uint32_t)(k * 512 + g2_p0 * 4);
                    ba ^= (ba >> 6) & 0x70;
                    ulonglong2 h01 = *(const ulonglong2*)(hsb + ba);
                    ulonglong2 h23 = *(const ulonglong2*)(hsb + (ba ^ 16));
                    ffma2(dacc[0], h01.x, wv);
                    ffma2(dacc[1], h01.y, wv);
                    ffma2(dacc[2], h23.x, wv);
                    ffma2(dacc[3], h23.y, wv);
                }
            }
            __syncthreads();   // protect hsh before next GEMM1-half overwrites it
        }

        // ---- epilogue: new_state = x + dx (in place in perc rows 0..31) ----
        {
            float bj = b2s[g2_c];
            #pragma unroll
            for (int i = 0; i < 4; ++i) {
                float lo, hi; unpack2(dacc[i], lo, hi);
                float2* dst = (float2*)(perc + g2_c * 128 + g2_p0 + 2 * i);
                float2 v = *dst;
                v.x += lo + bj;
                v.y += hi + bj;
                *dst = v;
            }
        }
        __syncthreads();

        // ---- per-pixel stats ----
        if (tid < 128) {
            const int p = tid;
            float best = perc[p];
            int arg = 0;
            #pragma unroll
            for (int c = 1; c < 10; ++c) {
                float v = perc[c * 128 + p];
                if (v > best) { best = v; arg = c; }
            }
            float factor = (arg != 0) ? 1.0f : 0.0f;
            float vals[32];
            float sum = 0.0f;
            #pragma unroll
            for (int c = 0; c < 32; ++c) {
                float v = perc[c * 128 + p];
                if (c >= 10) v *= factor;
                vals[c] = v;
                sum += v;
            }
            float mu = sum * (1.0f / 32.0f);
            float sq = 0.0f;
            #pragma unroll
            for (int c = 0; c < 32; ++c) {
                float d = vals[c] - mu;
                sq = fmaf(d, d, sq);
            }
            mus[p]  = mu;
            rss[p]  = rsqrtf(sq * (1.0f / 32.0f) + 1e-5f);
            invs[p] = factor;
        }
        __syncthreads();

        // ---- normalize + scale/shift + float4 store ----
        for (int v4 = tid; v4 < 32 * 32; v4 += THREADS) {
            int c = v4 >> 5, p4 = (v4 & 31) * 4;
            float4 xv = *(float4*)(perc + c * 128 + p4);
            float4 m4 = *(float4*)(mus + p4);
            float4 r4 = *(float4*)(rss + p4);
            float g = gs[c], bb = bss[c];
            if (c >= 10) {
                float4 f4 = *(float4*)(invs + p4);
                xv.x *= f4.x; xv.y *= f4.y; xv.z *= f4.z; xv.w *= f4.w;
            }
            float4 o4;
            o4.x = (xv.x - m4.x) * r4.x * g + bb;
            o4.y = (xv.y - m4.y) * r4.y * g + bb;
            o4.z = (xv.z - m4.z) * r4.z * g + bb;
            o4.w = (xv.w - m4.w) * r4.w * g + bb;
            *(float4*)(ob + (c * 128 + y) * 128 + p4) = o4;
        }
        __syncthreads();
    }
}

extern "C" void kernel_launch(void* const* d_in, const int* in_sizes, int n_in,
                              void* d_out, int out_size)
{
    const float* x     = (const float*)d_in[0];
    const float* w1    = (const float*)d_in[1];
    const float* b1    = (const float*)d_in[2];
    const float* w2    = (const float*)d_in[3];
    const float* b2    = (const float*)d_in[4];
    const float* gamma = (const float*)d_in[5];
    const float* beta  = (const float*)d_in[6];
    float* out = (float*)d_out;

    const size_t smem_bytes = (size_t)SM_TOTAL * sizeof(float);   // 223,616 B
    cudaFuncSetAttribute(cellnn_kernel,
                         cudaFuncAttributeMaxDynamicSharedMemorySize,
                         (int)smem_bytes);

    cellnn_kernel<<<1024, THREADS, smem_bytes>>>(x, w1, b1, w2, b2, gamma, beta, out);
}

// round 7
// speedup vs baseline: 1.0776x; 1.0776x over previous
#include <cuda_runtime.h>
#include <cstdint>

#define THREADS 1024
#define ROWS_PER_BLOCK 8

typedef unsigned long long ull;

// ---------------- SMEM layout (byte offsets) ----------------
#define SM_PERCP 0         // [56 kp][128 px] float2  (57,344 B)  bit7->bit4 swizzle
#define SM_W1P   57344     // [56 kp][128 o ] float2  (57,344 B)
#define SM_HSP   114688    // [64 kp][128 px] float2  (65,536 B)  row-XOR swizzle
#define SM_W2P   180224    // [64 kp][32 c  ] float2  (16,384 B)
#define SM_NS    196608    // [32 c][132 px] float    (16,896 B)
#define SM_B1    213504    // 128 f
#define SM_B2    214016    // 32 f
#define SM_G     214144
#define SM_BETA  214272
#define SM_MU    214400    // 128 f
#define SM_RS    214912
#define SM_INV   215424
#define SM_TOTAL 215936

__device__ __forceinline__ void ffma2(ull& d, ull a, ull b) {
    asm("fma.rn.f32x2 %0, %1, %2, %0;" : "+l"(d) : "l"(a), "l"(b));
}
__device__ __forceinline__ void unpack2(ull p, float& lo, float& hi) {
    asm("mov.b64 {%0, %1}, %2;" : "=f"(lo), "=f"(hi) : "l"(p));
}

// perceive value: channel k (0..111) at pixel (y, m)
__device__ __forceinline__ float perc_val(const float* __restrict__ xb, int y, int m, int k) {
    if (k < 32) return xb[(k * 128 + y) * 128 + m];
    int kk = k - 32;
    int c = kk >> 3, s = kk & 7;
    int idx = s + (s >= 4 ? 1 : 0);          // skip center tap
    int ki = idx / 3;
    int dy = ki - 1, dxx = idx - ki * 3 - 1;
    int yy = y + dy, xx = m + dxx;
    if ((unsigned)yy < 128u && (unsigned)xx < 128u)
        return xb[(c * 128 + yy) * 128 + xx];
    return 0.0f;
}

extern __shared__ char smem[];

__global__ void __launch_bounds__(THREADS, 1)
cellnn_kernel(const float* __restrict__ x,
              const float* __restrict__ w1,
              const float* __restrict__ b1,
              const float* __restrict__ w2,
              const float* __restrict__ b2,
              const float* __restrict__ gamma,
              const float* __restrict__ beta,
              float* __restrict__ out)
{
    float* b1s  = (float*)(smem + SM_B1);
    float* b2s  = (float*)(smem + SM_B2);
    float* gs   = (float*)(smem + SM_G);
    float* bts  = (float*)(smem + SM_BETA);
    float* mus  = (float*)(smem + SM_MU);
    float* rss  = (float*)(smem + SM_RS);
    float* invs = (float*)(smem + SM_INV);
    float* ns   = (float*)(smem + SM_NS);

    const int tid  = threadIdx.x;
    const int lane = tid & 31;
    const int warp = tid >> 5;

    // ---- stage w1p[kp][o] = (w1[o][2kp], w1[o][2kp+1]) ----
    #pragma unroll
    for (int it = 0; it < 14; ++it) {
        int i = it * THREADS + tid;          // i < 14336
        int k = i >> 7, o = i & 127;
        float v = w1[o * 112 + k];           // L2-served strided read
        *(float*)(smem + SM_W1P + (k >> 1) * 1024 + o * 8 + (k & 1) * 4) = v;
    }
    // ---- stage w2p[kp][c] = (w2[c][2kp], w2[c][2kp+1]) ----
    {
        int i = tid;                         // 4096 = 4*1024
        #pragma unroll
        for (int it = 0; it < 4; ++it, i += THREADS) {
            int k = i >> 5, c = i & 31;
            float v = w2[c * 128 + k];
            *(float*)(smem + SM_W2P + (k >> 1) * 256 + c * 8 + (k & 1) * 4) = v;
        }
    }
    if (tid < 128) b1s[tid] = b1[tid];
    if (tid < 32) { b2s[tid] = b2[tid]; gs[tid] = gamma[tid]; bts[tid] = beta[tid]; }

    const int row0 = blockIdx.x * ROWS_PER_BLOCK;
    const int bi   = row0 >> 7;
    const float* xb = x   + (size_t)bi * 32 * 128 * 128;
    float*       ob = out + (size_t)bi * 32 * 128 * 128;

    // GEMM1 mapping: 32 warps, warp tile 32px x 16o; thread 8px x 2o
    const int g1_p0 = ((warp & 3) * 4 + (lane & 3)) * 8;     // 8 px
    const int g1_o0 = ((warp >> 2) * 8 + (lane >> 2)) * 2;   // 2 o
    // percp bit7->bit4 swizzle: per-thread constant chunk offsets
    uint32_t co[4];
    {
        uint32_t m = (uint32_t)((g1_p0 * 8) >> 3) & 0x10;    // bit7 of p0*8 -> bit4
        #pragma unroll
        for (int i = 0; i < 4; ++i) co[i] = (uint32_t)(g1_p0 * 8 + i * 16) ^ m;
    }
    const uint32_t g1_wo = (uint32_t)(g1_o0 * 8);            // w1p offset within row
    // GEMM2 mapping: warp tile 16px x 8c; thread 4px x 1c
    const int g2_p0 = ((warp & 7) * 4 + (lane & 3)) * 4;     // 4 px
    const int g2_c  = (warp >> 3) * 8 + (lane >> 2);         // 1 c

    __syncthreads();

    for (int r = 0; r < ROWS_PER_BLOCK; ++r) {
        const int y = (row0 & 127) + r;

        // ---- build percp[kp][px] = (perc[2kp][px], perc[2kp+1][px]) ----
        #pragma unroll
        for (int it = 0; it < 14; ++it) {
            int i = it * THREADS + tid;      // i < 14336
            int k = i >> 7, px = i & 127;
            float v = perc_val(xb, y, px, k);
            uint32_t a = (uint32_t)((k >> 1) * 1024 + px * 8 + (k & 1) * 4);
            a ^= (a >> 3) & 0x10;
            *(float*)(smem + SM_PERCP + a) = v;
        }
        __syncthreads();

        // ---- GEMM1: h[128px][128o], k-pairwise FFMA2 ----
        {
            ull acc[8][2];
            #pragma unroll
            for (int i = 0; i < 8; ++i) { acc[i][0] = 0ull; acc[i][1] = 0ull; }

            const char* pp = smem + SM_PERCP;
            const char* pw = smem + SM_W1P + g1_wo;
            #pragma unroll 2
            for (int kp = 0; kp < 56; ++kp) {
                uint32_t base = (uint32_t)kp << 10;
                ulonglong2 A0 = *(const ulonglong2*)(pp + base + co[0]);
                ulonglong2 A1 = *(const ulonglong2*)(pp + base + co[1]);
                ulonglong2 A2 = *(const ulonglong2*)(pp + base + co[2]);
                ulonglong2 A3 = *(const ulonglong2*)(pp + base + co[3]);
                ulonglong2 Wv = *(const ulonglong2*)(pw + base);
                ffma2(acc[0][0], A0.x, Wv.x);  ffma2(acc[0][1], A0.x, Wv.y);
                ffma2(acc[1][0], A0.y, Wv.x);  ffma2(acc[1][1], A0.y, Wv.y);
                ffma2(acc[2][0], A1.x, Wv.x);  ffma2(acc[2][1], A1.x, Wv.y);
                ffma2(acc[3][0], A1.y, Wv.x);  ffma2(acc[3][1], A1.y, Wv.y);
                ffma2(acc[4][0], A2.x, Wv.x);  ffma2(acc[4][1], A2.x, Wv.y);
                ffma2(acc[5][0], A2.y, Wv.x);  ffma2(acc[5][1], A2.y, Wv.y);
                ffma2(acc[6][0], A3.x, Wv.x);  ffma2(acc[6][1], A3.x, Wv.y);
                ffma2(acc[7][0], A3.y, Wv.x);  ffma2(acc[7][1], A3.y, Wv.y);
            }
            // epilogue: h = relu(lo+hi+b1), write hsp[o0>>1][px] = (h_o0, h_o0+1)
            float b0 = b1s[g1_o0], b1v = b1s[g1_o0 + 1];
            int row = g1_o0 >> 1;
            char* sb = smem + SM_HSP + row * 1024;
            uint32_t mask = (uint32_t)(row & 7) << 4;
            #pragma unroll
            for (int i = 0; i < 8; ++i) {
                float l0, h0, l1, h1;
                unpack2(acc[i][0], l0, h0);
                unpack2(acc[i][1], l1, h1);
                float hv0 = fmaxf(l0 + h0 + b0, 0.0f);
                float hv1 = fmaxf(l1 + h1 + b1v, 0.0f);
                uint32_t a = ((uint32_t)((g1_p0 + i) * 8)) ^ mask;
                *(float2*)(sb + a) = make_float2(hv0, hv1);
            }
        }
        __syncthreads();

        // ---- GEMM2: dx[128px][32c], k-pairwise; ns = x + dx ----
        {
            ull dacc[4] = {0ull, 0ull, 0ull, 0ull};
            const char* ph = smem + SM_HSP;
            const char* pw = smem + SM_W2P + g2_c * 8;
            const uint32_t poff = (uint32_t)(g2_p0 * 8);
            #pragma unroll 4
            for (int kp = 0; kp < 64; ++kp) {
                uint32_t base = (uint32_t)kp << 10;
                uint32_t am = ((uint32_t)kp & 7) << 4;
                uint32_t o0 = poff ^ am;
                ulonglong2 A0 = *(const ulonglong2*)(ph + base + o0);
                ulonglong2 A1 = *(const ulonglong2*)(ph + base + (o0 ^ 16));
                ull wv = *(const ull*)(pw + kp * 256);
                ffma2(dacc[0], A0.x, wv);
                ffma2(dacc[1], A0.y, wv);
                ffma2(dacc[2], A1.x, wv);
                ffma2(dacc[3], A1.y, wv);
            }
            float bj = b2s[g2_c];
            float4 o4;
            float* po = &o4.x;
            #pragma unroll
            for (int i = 0; i < 4; ++i) {
                float lo, hi; unpack2(dacc[i], lo, hi);
                int px = g2_p0 + i;
                uint32_t a = (uint32_t)((g2_c >> 1) * 1024 + px * 8 + (g2_c & 1) * 4);
                a ^= (a >> 3) & 0x10;
                float xc = *(const float*)(smem + SM_PERCP + a);
                po[i] = lo + hi + bj + xc;
            }
            *(float4*)(ns + g2_c * 132 + g2_p0) = o4;
        }
        __syncthreads();

        // ---- per-pixel stats ----
        if (tid < 128) {
            const int p = tid;
            float best = ns[p];
            int arg = 0;
            #pragma unroll
            for (int c = 1; c < 10; ++c) {
                float v = ns[c * 132 + p];
                if (v > best) { best = v; arg = c; }
            }
            float factor = (arg != 0) ? 1.0f : 0.0f;
            float sum = 0.0f;
            float vals[32];
            #pragma unroll
            for (int c = 0; c < 32; ++c) {
                float v = ns[c * 132 + p];
                if (c >= 10) v *= factor;
                vals[c] = v;
                sum += v;
            }
            float mu = sum * (1.0f / 32.0f);
            float sq = 0.0f;
            #pragma unroll
            for (int c = 0; c < 32; ++c) {
                float d = vals[c] - mu;
                sq = fmaf(d, d, sq);
            }
            mus[p]  = mu;
            rss[p]  = rsqrtf(sq * (1.0f / 32.0f) + 1e-5f);
            invs[p] = factor;
        }
        __syncthreads();

        // ---- normalize + scale/shift + float4 store (1 float4/thread) ----
        {
            int c = tid >> 5, p4 = (tid & 31) * 4;
            float4 xv = *(float4*)(ns + c * 132 + p4);
            float4 m4 = *(float4*)(mus + p4);
            float4 r4 = *(float4*)(rss + p4);
            float g = gs[c], bb = bts[c];
            if (c >= 10) {
                float4 f4 = *(float4*)(invs + p4);
                xv.x *= f4.x; xv.y *= f4.y; xv.z *= f4.z; xv.w *= f4.w;
            }
            float4 o4;
            o4.x = (xv.x - m4.x) * r4.x * g + bb;
            o4.y = (xv.y - m4.y) * r4.y * g + bb;
            o4.z = (xv.z - m4.z) * r4.z * g + bb;
            o4.w = (xv.w - m4.w) * r4.w * g + bb;
            *(float4*)(ob + (c * 128 + y) * 128 + p4) = o4;
        }
        __syncthreads();
    }
}

extern "C" void kernel_launch(void* const* d_in, const int* in_sizes, int n_in,
                              void* d_out, int out_size)
{
    const float* x     = (const float*)d_in[0];
    const float* w1    = (const float*)d_in[1];
    const float* b1    = (const float*)d_in[2];
    const float* w2    = (const float*)d_in[3];
    const float* b2    = (const float*)d_in[4];
    const float* gamma = (const float*)d_in[5];
    const float* beta  = (const float*)d_in[6];
    float* out = (float*)d_out;

    cudaFuncSetAttribute(cellnn_kernel,
                         cudaFuncAttributeMaxDynamicSharedMemorySize, SM_TOTAL);

    cellnn_kernel<<<1024, THREADS, SM_TOTAL>>>(x, w1, b1, w2, b2, gamma, beta, out);
}

// round 8
// speedup vs baseline: 1.2718x; 1.1802x over previous
#include <cuda_runtime.h>
#include <cstdint>

#define THREADS 1024
#define ROWS_PER_BLOCK 8

typedef unsigned long long ull;

// ---------------- SMEM layout (byte offsets) ----------------
#define SM_PERCP 0         // [56 kp][128 px] float2, bit7->bit4 swizzle   57344
#define SM_W1P   57344     // [56 kp][128 o ] float2, bit7->bit4 swizzle   57344
#define SM_HSP   114688    // [64 kp][128 px] float2, row-XOR swizzle      65536
#define SM_W2P   180224    // [64 kp][32 c  ] float2                       16384
#define SM_NS    196608    // [32 c][136 px] float                         17408
#define SM_PVS   214016    // [4][128] partial vis sum
#define SM_PHS   216064    // [4][128] partial hid sum
#define SM_PVQ   218112    // [4][128] partial vis sumsq
#define SM_PHQ   220160    // [4][128] partial hid sumsq
#define SM_PMX   222208    // [2][128] partial max (c<10)
#define SM_PAG   223232    // [2][128] partial arg (int)
#define SM_B1    224256
#define SM_B2    224768
#define SM_G     224896
#define SM_BETA  225024
#define SM_MU    225152
#define SM_RS    225664
#define SM_INV   226176
#define SM_TOTAL 226688

__device__ __forceinline__ void ffma2(ull& d, ull a, ull b) {
    asm("fma.rn.f32x2 %0, %1, %2, %0;" : "+l"(d) : "l"(a), "l"(b));
}
__device__ __forceinline__ void unpack2(ull p, float& lo, float& hi) {
    asm("mov.b64 {%0, %1}, %2;" : "=f"(lo), "=f"(hi) : "l"(p));
}

// perceive value: channel k (0..111) at pixel (y, m)
__device__ __forceinline__ float perc_val(const float* __restrict__ xb, int y, int m, int k) {
    if (k < 32) return xb[(k * 128 + y) * 128 + m];
    int kk = k - 32;
    int c = kk >> 3, s = kk & 7;
    int idx = s + (s >= 4 ? 1 : 0);          // skip center tap
    int ki = idx / 3;
    int dy = ki - 1, dxx = idx - ki * 3 - 1;
    int yy = y + dy, xx = m + dxx;
    if ((unsigned)yy < 128u && (unsigned)xx < 128u)
        return xb[(c * 128 + yy) * 128 + xx];
    return 0.0f;
}

extern __shared__ char smem[];

__global__ void __launch_bounds__(THREADS, 1)
cellnn_kernel(const float* __restrict__ x,
              const float* __restrict__ w1,
              const float* __restrict__ b1,
              const float* __restrict__ w2,
              const float* __restrict__ b2,
              const float* __restrict__ gamma,
              const float* __restrict__ beta,
              float* __restrict__ out)
{
    float* b1s  = (float*)(smem + SM_B1);
    float* b2s  = (float*)(smem + SM_B2);
    float* gs   = (float*)(smem + SM_G);
    float* bts  = (float*)(smem + SM_BETA);
    float* mus  = (float*)(smem + SM_MU);
    float* rss  = (float*)(smem + SM_RS);
    float* invs = (float*)(smem + SM_INV);
    float* ns   = (float*)(smem + SM_NS);

    const int tid  = threadIdx.x;
    const int lane = tid & 31;
    const int warp = tid >> 5;

    // ---- stage w1p[kp][o] = (w1[o][2kp], w1[o][2kp+1]), bit7->bit4 swizzle ----
    #pragma unroll
    for (int it = 0; it < 14; ++it) {
        int i = it * THREADS + tid;          // i < 14336: k = i>>7, o = i&127
        int k = i >> 7, o = i & 127;
        float v = w1[o * 112 + k];
        uint32_t a = (uint32_t)((k >> 1) * 1024 + o * 8 + (k & 1) * 4);
        a ^= (a >> 3) & 0x10;
        *(float*)(smem + SM_W1P + a) = v;
    }
    // ---- stage w2p[kp][c] = (w2[c][2kp], w2[c][2kp+1]) ----
    {
        int i = tid;
        #pragma unroll
        for (int it = 0; it < 4; ++it, i += THREADS) {
            int k = i >> 5, c = i & 31;
            float v = w2[c * 128 + k];
            *(float*)(smem + SM_W2P + (k >> 1) * 256 + c * 8 + (k & 1) * 4) = v;
        }
    }
    if (tid < 128) b1s[tid] = b1[tid];
    if (tid < 32) { b2s[tid] = b2[tid]; gs[tid] = gamma[tid]; bts[tid] = beta[tid]; }

    const int row0 = blockIdx.x * ROWS_PER_BLOCK;
    const int bi   = row0 >> 7;
    const float* xb = x   + (size_t)bi * 32 * 128 * 128;
    float*       ob = out + (size_t)bi * 32 * 128 * 128;

    // ---- GEMM1 mapping: thread 4px x 4o; warp 16px x 32o; 32 warps cover 128x128
    const int g1_p0 = ((warp & 7) * 4 + (lane & 3)) * 4;
    const int g1_o0 = ((warp >> 3) * 8 + (lane >> 2)) * 4;
    uint32_t aco0, aco1, wco0, wco1;
    {
        uint32_t b = (uint32_t)(g1_p0 * 8);
        uint32_t m = (b & 0x80) >> 3;
        aco0 = b ^ m;
        aco1 = (b + 16) ^ m;
        uint32_t wb = (uint32_t)(g1_o0 * 8);
        uint32_t wm = (wb & 0x80) >> 3;
        wco0 = wb ^ wm;
        wco1 = (wb + 16) ^ wm;
    }
    // ---- GEMM2 mapping: thread 4px x 1c; warp 16px x 8c
    const int g2_p0 = ((warp & 7) * 4 + (lane & 3)) * 4;
    const int g2_c  = (warp >> 3) * 8 + (lane >> 2);

    __syncthreads();

    for (int r = 0; r < ROWS_PER_BLOCK; ++r) {
        const int y = (row0 & 127) + r;

        // ---- build percp[kp][px] = (perc[2kp][px], perc[2kp+1][px]) ----
        #pragma unroll
        for (int it = 0; it < 7; ++it) {
            int i = it * THREADS + tid;      // i < 7168: kp = i>>7, px = i&127
            int kp = i >> 7, px = i & 127;
            float v0 = perc_val(xb, y, px, 2 * kp);
            float v1 = perc_val(xb, y, px, 2 * kp + 1);
            uint32_t a = (uint32_t)(kp * 1024 + px * 8);
            a ^= (a >> 3) & 0x10;
            *(float2*)(smem + SM_PERCP + a) = make_float2(v0, v1);
        }
        __syncthreads();

        // ---- GEMM1: h[128px][128o], k-pairwise FFMA2, 4px x 4o ----
        {
            ull acc[4][4];
            #pragma unroll
            for (int i = 0; i < 4; ++i)
                #pragma unroll
                for (int j = 0; j < 4; ++j) acc[i][j] = 0ull;

            const char* pA0 = smem + SM_PERCP + aco0;
            const char* pA1 = smem + SM_PERCP + aco1;
            const char* pW0 = smem + SM_W1P + wco0;
            const char* pW1 = smem + SM_W1P + wco1;
            #pragma unroll 2
            for (int kp = 0; kp < 56; ++kp) {
                uint32_t base = (uint32_t)kp << 10;
                ulonglong2 A0 = *(const ulonglong2*)(pA0 + base);   // px0, px0+1
                ulonglong2 A1 = *(const ulonglong2*)(pA1 + base);   // px0+2, px0+3
                ulonglong2 W0 = *(const ulonglong2*)(pW0 + base);   // o0, o0+1
                ulonglong2 W1 = *(const ulonglong2*)(pW1 + base);   // o0+2, o0+3
                ffma2(acc[0][0], A0.x, W0.x);  ffma2(acc[0][1], A0.x, W0.y);
                ffma2(acc[0][2], A0.x, W1.x);  ffma2(acc[0][3], A0.x, W1.y);
                ffma2(acc[1][0], A0.y, W0.x);  ffma2(acc[1][1], A0.y, W0.y);
                ffma2(acc[1][2], A0.y, W1.x);  ffma2(acc[1][3], A0.y, W1.y);
                ffma2(acc[2][0], A1.x, W0.x);  ffma2(acc[2][1], A1.x, W0.y);
                ffma2(acc[2][2], A1.x, W1.x);  ffma2(acc[2][3], A1.x, W1.y);
                ffma2(acc[3][0], A1.y, W0.x);  ffma2(acc[3][1], A1.y, W0.y);
                ffma2(acc[3][2], A1.y, W1.x);  ffma2(acc[3][3], A1.y, W1.y);
            }
            // epilogue: h = relu(lo+hi+b1); hsp[row][px] = (h_even_o, h_odd_o)
            #pragma unroll
            for (int jp = 0; jp < 2; ++jp) {
                int o_e = g1_o0 + 2 * jp;
                float be = b1s[o_e], bo = b1s[o_e + 1];
                int row = (g1_o0 >> 1) + jp;
                char* sb = smem + SM_HSP + row * 1024;
                uint32_t msk = (uint32_t)(row & 7) << 4;
                float hv[8];
                #pragma unroll
                for (int i = 0; i < 4; ++i) {
                    float lo, hi;
                    unpack2(acc[i][2 * jp], lo, hi);
                    hv[2 * i] = fmaxf(lo + hi + be, 0.0f);
                    unpack2(acc[i][2 * jp + 1], lo, hi);
                    hv[2 * i + 1] = fmaxf(lo + hi + bo, 0.0f);
                }
                uint32_t a01 = ((uint32_t)(g1_p0 * 8)) ^ msk;
                uint32_t a23 = ((uint32_t)(g1_p0 * 8 + 16)) ^ msk;
                *(float4*)(sb + a01) = make_float4(hv[0], hv[1], hv[2], hv[3]);
                *(float4*)(sb + a23) = make_float4(hv[4], hv[5], hv[6], hv[7]);
            }
        }
        __syncthreads();

        // ---- GEMM2: dx[128px][32c], k-pairwise; ns = x + dx + b2 ----
        {
            ull dacc[4] = {0ull, 0ull, 0ull, 0ull};
            const char* ph = smem + SM_HSP;
            const char* pw = smem + SM_W2P + g2_c * 8;
            const uint32_t poff = (uint32_t)(g2_p0 * 8);
            #pragma unroll 4
            for (int kp = 0; kp < 64; ++kp) {
                uint32_t base = (uint32_t)kp << 10;
                uint32_t o0 = poff ^ (((uint32_t)kp & 7) << 4);
                ulonglong2 A0 = *(const ulonglong2*)(ph + base + o0);
                ulonglong2 A1 = *(const ulonglong2*)(ph + base + (o0 ^ 16));
                ull wv = *(const ull*)(pw + kp * 256);
                ffma2(dacc[0], A0.x, wv);
                ffma2(dacc[1], A0.y, wv);
                ffma2(dacc[2], A1.x, wv);
                ffma2(dacc[3], A1.y, wv);
            }
            float bj = b2s[g2_c];
            const char* pcb = smem + SM_PERCP + (g2_c >> 1) * 1024 + (g2_c & 1) * 4;
            float4 o4;
            float* po = &o4.x;
            #pragma unroll
            for (int i = 0; i < 4; ++i) {
                float lo, hi;
                unpack2(dacc[i], lo, hi);
                uint32_t a = (uint32_t)((g2_p0 + i) * 8);
                a ^= (a >> 3) & 0x10;
                float xc = *(const float*)(pcb + a);
                po[i] = lo + hi + bj + xc;
            }
            *(float4*)(ns + g2_c * 136 + g2_p0) = o4;
        }
        __syncthreads();

        // ---- stats partial pass: 512 threads, 8 channels each ----
        if (tid < 512) {
            int g = tid >> 7, p = tid & 127;
            const float* nsg = ns + g * 8 * 136 + p;
            float sv = 0.0f, sh = 0.0f, qv = 0.0f, qh = 0.0f;
            float best = -3.4e38f;
            int arg = 0;
            if (g == 0) {
                #pragma unroll
                for (int cc = 0; cc < 8; ++cc) {
                    float v = nsg[cc * 136];
                    sv += v; qv = fmaf(v, v, qv);
                    if (v > best) { best = v; arg = cc; }
                }
            } else if (g == 1) {
                #pragma unroll
                for (int cc = 0; cc < 2; ++cc) {
                    float v = nsg[cc * 136];
                    sv += v; qv = fmaf(v, v, qv);
                    if (v > best) { best = v; arg = 8 + cc; }
                }
                #pragma unroll
                for (int cc = 2; cc < 8; ++cc) {
                    float v = nsg[cc * 136];
                    sh += v; qh = fmaf(v, v, qh);
                }
            } else {
                #pragma unroll
                for (int cc = 0; cc < 8; ++cc) {
                    float v = nsg[cc * 136];
                    sh += v; qh = fmaf(v, v, qh);
                }
            }
            ((float*)(smem + SM_PVS))[g * 128 + p] = sv;
            ((float*)(smem + SM_PHS))[g * 128 + p] = sh;
            ((float*)(smem + SM_PVQ))[g * 128 + p] = qv;
            ((float*)(smem + SM_PHQ))[g * 128 + p] = qh;
            if (g < 2) {
                ((float*)(smem + SM_PMX))[g * 128 + p] = best;
                ((int*)(smem + SM_PAG))[g * 128 + p] = arg;
            }
        }
        __syncthreads();

        // ---- stats combine: 128 threads ----
        if (tid < 128) {
            int p = tid;
            const float* pvs = (const float*)(smem + SM_PVS);
            const float* phs = (const float*)(smem + SM_PHS);
            const float* pvq = (const float*)(smem + SM_PVQ);
            const float* phq = (const float*)(smem + SM_PHQ);
            const float* pmx = (const float*)(smem + SM_PMX);
            const int*   pag = (const int*)(smem + SM_PAG);
            float b0 = pmx[p], b1v = pmx[128 + p];
            int arg = (b1v > b0) ? pag[128 + p] : pag[p];
            float f = (arg != 0) ? 1.0f : 0.0f;
            float s = pvs[p] + pvs[128 + p] + pvs[256 + p] + pvs[384 + p]
                    + f * (phs[p] + phs[128 + p] + phs[256 + p] + phs[384 + p]);
            float q = pvq[p] + pvq[128 + p] + pvq[256 + p] + pvq[384 + p]
                    + f * (phq[p] + phq[128 + p] + phq[256 + p] + phq[384 + p]);
            float mu = s * (1.0f / 32.0f);
            float var = q * (1.0f / 32.0f) - mu * mu;
            mus[p]  = mu;
            rss[p]  = rsqrtf(var + 1e-5f);
            invs[p] = f;
        }
        __syncthreads();

        // ---- normalize + scale/shift + float4 store ----
        {
            int c = tid >> 5, p4 = (tid & 31) * 4;
            float4 xv = *(float4*)(ns + c * 136 + p4);
            float4 m4 = *(float4*)(mus + p4);
            float4 r4 = *(float4*)(rss + p4);
            float g = gs[c], bb = bts[c];
            if (c >= 10) {
                float4 f4 = *(float4*)(invs + p4);
                xv.x *= f4.x; xv.y *= f4.y; xv.z *= f4.z; xv.w *= f4.w;
            }
            float4 o4;
            o4.x = (xv.x - m4.x) * r4.x * g + bb;
            o4.y = (xv.y - m4.y) * r4.y * g + bb;
            o4.z = (xv.z - m4.z) * r4.z * g + bb;
            o4.w = (xv.w - m4.w) * r4.w * g + bb;
            *(float4*)(ob + (c * 128 + y) * 128 + p4) = o4;
        }
        __syncthreads();
    }
}

extern "C" void kernel_launch(void* const* d_in, const int* in_sizes, int n_in,
                              void* d_out, int out_size)
{
    const float* x     = (const float*)d_in[0];
    const float* w1    = (const float*)d_in[1];
    const float* b1    = (const float*)d_in[2];
    const float* w2    = (const float*)d_in[3];
    const float* b2    = (const float*)d_in[4];
    const float* gamma = (const float*)d_in[5];
    const float* beta  = (const float*)d_in[6];
    float* out = (float*)d_out;

    cudaFuncSetAttribute(cellnn_kernel,
                         cudaFuncAttributeMaxDynamicSharedMemorySize, SM_TOTAL);

    cellnn_kernel<<<1024, THREADS, SM_TOTAL>>>(x, w1, b1, w2, b2, gamma, beta, out);
}

// round 11
// speedup vs baseline: 1.6726x; 1.3151x over previous
#include <cuda_runtime.h>
#include <cstdint>

#define THREADS 256
#define ROWS_PER_BLOCK 8

typedef unsigned long long ull;

// ---------------- SMEM layout (byte offsets) ----------------
#define SM_PERCP 0         // [56 kp][128 px] float2, SWZ1                 57344
#define SM_W1P   57344     // [56 kp][128 o ] float2, SWZ1                 57344
#define SM_HSP   114688    // [64 r ][128 px] float2, SWZ1 ^ KMASK(r)      65536
#define SM_W2P   180224    // [64 kp][32 c  ] float2                       16384
#define SM_NS    196608    // [32 c][136 px] float                         17408
#define SM_PVS   214016    // [2][128]
#define SM_PHS   215040
#define SM_PVQ   216064
#define SM_PHQ   217088
#define SM_PMX   218112    // [128]
#define SM_PAG   218624    // [128] int
#define SM_B1    219136
#define SM_B2    219648
#define SM_G     219776
#define SM_BETA  219904
#define SM_MU    220032
#define SM_RS    220544
#define SM_INV   221056
#define SM_TOTAL 221568

// swizzle within a 1024B row: byte bits 7-8 -> bank-group bits 4-5
#define SWZ1(o) ((uint32_t)(o) ^ ((((uint32_t)(o)) >> 3) & 0x30u))
// hsp row-dependent mask: r>>2 bits -> addr bits 4,5,8
#define KMASK(r) ((((((uint32_t)(r)) >> 2) & 3u) << 4) ^ (((((uint32_t)(r)) >> 2) & 4u) << 6))

__device__ __forceinline__ void ffma2(ull& d, ull a, ull b) {
    asm("fma.rn.f32x2 %0, %1, %2, %0;" : "+l"(d) : "l"(a), "l"(b));
}
__device__ __forceinline__ void unpack2(ull p, float& lo, float& hi) {
    asm("mov.b64 {%0, %1}, %2;" : "=f"(lo), "=f"(hi) : "l"(p));
}

// perceive value: channel k (0..111) at pixel (y, m)
__device__ __forceinline__ float perc_val(const float* __restrict__ xb, int y, int m, int k) {
    if (k < 32) return xb[(k * 128 + y) * 128 + m];
    int kk = k - 32;
    int c = kk >> 3, s = kk & 7;
    int idx = s + (s >= 4 ? 1 : 0);          // skip center tap
    int ki = idx / 3;
    int dy = ki - 1, dxx = idx - ki * 3 - 1;
    int yy = y + dy, xx = m + dxx;
    if ((unsigned)yy < 128u && (unsigned)xx < 128u)
        return xb[(c * 128 + yy) * 128 + xx];
    return 0.0f;
}

extern __shared__ char smem[];

__global__ void __launch_bounds__(THREADS, 1)
cellnn_kernel(const float* __restrict__ x,
              const float* __restrict__ w1,
              const float* __restrict__ b1,
              const float* __restrict__ w2,
              const float* __restrict__ b2,
              const float* __restrict__ gamma,
              const float* __restrict__ beta,
              float* __restrict__ out)
{
    float* b1s  = (float*)(smem + SM_B1);
    float* b2s  = (float*)(smem + SM_B2);
    float* gs   = (float*)(smem + SM_G);
    float* bts  = (float*)(smem + SM_BETA);
    float* mus  = (float*)(smem + SM_MU);
    float* rss  = (float*)(smem + SM_RS);
    float* invs = (float*)(smem + SM_INV);
    float* ns   = (float*)(smem + SM_NS);

    const int tid  = threadIdx.x;
    const int lane = tid & 31;
    const int warp = tid >> 5;

    // ---- stage w1p[kp][o] = (w1[o][2kp], w1[o][2kp+1]), SWZ1 on o-offset ----
    #pragma unroll
    for (int it = 0; it < 56; ++it) {
        int i = it * THREADS + tid;          // i < 14336: k = i>>7, o = i&127
        int k = i >> 7, o = i & 127;
        float v = w1[o * 112 + k];
        uint32_t a = (uint32_t)((k >> 1) * 1024) + SWZ1((uint32_t)(o * 8)) + (uint32_t)((k & 1) * 4);
        *(float*)(smem + SM_W1P + a) = v;
    }
    // ---- stage w2p[kp][c] = (w2[c][2kp], w2[c][2kp+1]) ----
    #pragma unroll
    for (int it = 0; it < 16; ++it) {
        int i = it * THREADS + tid;          // i < 4096
        int k = i >> 5, c = i & 31;
        float v = w2[c * 128 + k];
        *(float*)(smem + SM_W2P + (k >> 1) * 256 + c * 8 + (k & 1) * 4) = v;
    }
    if (tid < 128) b1s[tid] = b1[tid];
    if (tid < 32) { b2s[tid] = b2[tid]; gs[tid] = gamma[tid]; bts[tid] = beta[tid]; }

    const int row0 = blockIdx.x * ROWS_PER_BLOCK;
    const int bi   = row0 >> 7;
    const float* xb = x   + (size_t)bi * 32 * 128 * 128;
    float*       ob = out + (size_t)bi * 32 * 128 * 128;

    // ---- GEMM1 mapping: thread 8px x 8o; warp 32px x 64o; 8 warps cover 128x128
    const int g1_p0 = ((warp & 3) * 4 + (lane & 3)) * 8;       // 8 px
    const int g1_o0 = ((warp >> 2) * 8 + (lane >> 2)) * 8;     // 8 o
    uint32_t a_off[4], w_off[4];
    #pragma unroll
    for (int c = 0; c < 4; ++c) {
        a_off[c] = SWZ1((uint32_t)(g1_p0 * 8 + c * 16));
        w_off[c] = SWZ1((uint32_t)(g1_o0 * 8 + c * 16));
    }
    // hsp store offsets: rows r = g1_o0/2 + jp
    uint32_t h_off[4][4];
    #pragma unroll
    for (int jp = 0; jp < 4; ++jp) {
        uint32_t r = (uint32_t)(g1_o0 / 2 + jp);
        uint32_t km = KMASK(r);
        #pragma unroll
        for (int c = 0; c < 4; ++c)
            h_off[jp][c] = r * 1024 + (SWZ1((uint32_t)(g1_p0 * 8 + c * 16)) ^ km);
    }

    // ---- GEMM2 mapping: thread 4px x 4c; warp 32px x 16c; 8 warps cover 128x32
    const int g2_p0 = ((warp & 3) * 8 + (lane >> 2)) * 4;      // 4 px
    const int g2_c0 = ((warp >> 2) * 4 + (lane & 3)) * 4;      // 4 c
    const uint32_t g2_aoff0 = SWZ1((uint32_t)(g2_p0 * 8));
    const uint32_t g2_aoff1 = SWZ1((uint32_t)(g2_p0 * 8 + 16));

    __syncthreads();

    for (int r8 = 0; r8 < ROWS_PER_BLOCK; ++r8) {
        const int y = (row0 & 127) + r8;

        // ---- build percp[kp][px] = (perc[2kp][px], perc[2kp+1][px]) ----
        #pragma unroll
        for (int it = 0; it < 28; ++it) {
            int i = it * THREADS + tid;      // i < 7168
            int kp = i >> 7, px = i & 127;
            float v0 = perc_val(xb, y, px, 2 * kp);
            float v1 = perc_val(xb, y, px, 2 * kp + 1);
            uint32_t a = (uint32_t)(kp * 1024) + SWZ1((uint32_t)(px * 8));
            *(float2*)(smem + SM_PERCP + a) = make_float2(v0, v1);
        }
        __syncthreads();

        // ---- GEMM1: 8px x 8o, k-pairwise FFMA2 ----
        {
            ull acc[64];
            #pragma unroll
            for (int i = 0; i < 64; ++i) acc[i] = 0ull;

            const char* pp = smem + SM_PERCP;
            const char* pw = smem + SM_W1P;
            #pragma unroll 2
            for (int kp = 0; kp < 56; ++kp) {
                uint32_t base = (uint32_t)kp << 10;
                ull Av[8], Wv[8];
                {
                    ulonglong2 t;
                    t = *(const ulonglong2*)(pp + base + a_off[0]); Av[0] = t.x; Av[1] = t.y;
                    t = *(const ulonglong2*)(pp + base + a_off[1]); Av[2] = t.x; Av[3] = t.y;
                    t = *(const ulonglong2*)(pp + base + a_off[2]); Av[4] = t.x; Av[5] = t.y;
                    t = *(const ulonglong2*)(pp + base + a_off[3]); Av[6] = t.x; Av[7] = t.y;
                    t = *(const ulonglong2*)(pw + base + w_off[0]); Wv[0] = t.x; Wv[1] = t.y;
                    t = *(const ulonglong2*)(pw + base + w_off[1]); Wv[2] = t.x; Wv[3] = t.y;
                    t = *(const ulonglong2*)(pw + base + w_off[2]); Wv[4] = t.x; Wv[5] = t.y;
                    t = *(const ulonglong2*)(pw + base + w_off[3]); Wv[6] = t.x; Wv[7] = t.y;
                }
                #pragma unroll
                for (int i = 0; i < 8; ++i)
                    #pragma unroll
                    for (int j = 0; j < 8; ++j)
                        ffma2(acc[i * 8 + j], Av[i], Wv[j]);
            }
            // epilogue: h = relu(lo+hi+b1); pack (h_even_o, h_odd_o) pairs
            #pragma unroll
            for (int jp = 0; jp < 4; ++jp) {
                float be = b1s[g1_o0 + 2 * jp];
                float bo = b1s[g1_o0 + 2 * jp + 1];
                char* sb = smem + SM_HSP;
                #pragma unroll
                for (int c = 0; c < 4; ++c) {     // px pairs (2 px per chunk)
                    float l, h;
                    float4 v;
                    unpack2(acc[(2 * c) * 8 + 2 * jp], l, h);
                    v.x = fmaxf(l + h + be, 0.0f);
                    unpack2(acc[(2 * c) * 8 + 2 * jp + 1], l, h);
                    v.y = fmaxf(l + h + bo, 0.0f);
                    unpack2(acc[(2 * c + 1) * 8 + 2 * jp], l, h);
                    v.z = fmaxf(l + h + be, 0.0f);
                    unpack2(acc[(2 * c + 1) * 8 + 2 * jp + 1], l, h);
                    v.w = fmaxf(l + h + bo, 0.0f);
                    *(float4*)(sb + h_off[jp][c]) = v;
                }
            }
        }
        __syncthreads();

        // ---- GEMM2: 4px x 4c, k-pairwise; ns = x + dx + b2 ----
        {
            ull acc2[16];
            #pragma unroll
            for (int i = 0; i < 16; ++i) acc2[i] = 0ull;

            const char* ph = smem + SM_HSP;
            const char* pw = smem + SM_W2P + g2_c0 * 8;
            #pragma unroll 8
            for (int kp = 0; kp < 64; ++kp) {
                uint32_t km = KMASK(kp);
                uint32_t base = (uint32_t)(kp * 1024);
                ull Av[4], Wv[4];
                {
                    ulonglong2 t;
                    t = *(const ulonglong2*)(ph + base + (g2_aoff0 ^ km)); Av[0] = t.x; Av[1] = t.y;
                    t = *(const ulonglong2*)(ph + base + (g2_aoff1 ^ km)); Av[2] = t.x; Av[3] = t.y;
                    t = *(const ulonglong2*)(pw + kp * 256);      Wv[0] = t.x; Wv[1] = t.y;
                    t = *(const ulonglong2*)(pw + kp * 256 + 16); Wv[2] = t.x; Wv[3] = t.y;
                }
                #pragma unroll
                for (int j = 0; j < 4; ++j)
                    #pragma unroll
                    for (int i = 0; i < 4; ++i)
                        ffma2(acc2[j * 4 + i], Av[i], Wv[j]);
            }
            // residual + write ns
            #pragma unroll
            for (int j = 0; j < 4; ++j) {
                int c = g2_c0 + j;
                float bj = b2s[c];
                const char* pcb = smem + SM_PERCP + (c >> 1) * 1024 + (c & 1) * 4;
                float4 o4;
                float* po = &o4.x;
                #pragma unroll
                for (int i = 0; i < 4; ++i) {
                    float lo, hi;
                    unpack2(acc2[j * 4 + i], lo, hi);
                    float xc = *(const float*)(pcb + SWZ1((uint32_t)((g2_p0 + i) * 8)));
                    po[i] = lo + hi + bj + xc;
                }
                *(float4*)(ns + c * 136 + g2_p0) = o4;
            }
        }
        __syncthreads();

        // ---- stats partial pass: 2 groups of 128 threads, 16 ch each ----
        {
            int g = tid >> 7, p = tid & 127;
            const float* nsg = ns + g * 16 * 136 + p;
            float sv = 0.0f, sh = 0.0f, qv = 0.0f, qh = 0.0f;
            if (g == 0) {
                float best = -3.4e38f;
                int arg = 0;
                #pragma unroll
                for (int cc = 0; cc < 10; ++cc) {
                    float v = nsg[cc * 136];
                    sv += v; qv = fmaf(v, v, qv);
                    if (v > best) { best = v; arg = cc; }
                }
                #pragma unroll
                for (int cc = 10; cc < 16; ++cc) {
                    float v = nsg[cc * 136];
                    sh += v; qh = fmaf(v, v, qh);
                }
                ((float*)(smem + SM_PMX))[p] = best;
                ((int*)(smem + SM_PAG))[p] = arg;
            } else {
                #pragma unroll
                for (int cc = 0; cc < 16; ++cc) {
                    float v = nsg[cc * 136];
                    sh += v; qh = fmaf(v, v, qh);
                }
            }
            ((float*)(smem + SM_PVS))[g * 128 + p] = sv;
            ((float*)(smem + SM_PHS))[g * 128 + p] = sh;
            ((float*)(smem + SM_PVQ))[g * 128 + p] = qv;
            ((float*)(smem + SM_PHQ))[g * 128 + p] = qh;
        }
        __syncthreads();

        // ---- stats combine: 128 threads ----
        if (tid < 128) {
            int p = tid;
            const float* pvs = (const float*)(smem + SM_PVS);
            const float* phs = (const float*)(smem + SM_PHS);
            const float* pvq = (const float*)(smem + SM_PVQ);
            const float* phq = (const float*)(smem + SM_PHQ);
            int arg = ((const int*)(smem + SM_PAG))[p];
            float f = (arg != 0) ? 1.0f : 0.0f;
            float s = pvs[p] + f * (phs[p] + phs[128 + p]);
            float q = pvq[p] + f * (phq[p] + phq[128 + p]);
            float mu = s * (1.0f / 32.0f);
            float var = q * (1.0f / 32.0f) - mu * mu;
            mus[p]  = mu;
            rss[p]  = rsqrtf(var + 1e-5f);
            invs[p] = f;
        }
        __syncthreads();

        // ---- normalize + scale/shift + store (16 floats / thread) ----
        {
            int c = tid >> 3, p0 = (tid & 7) * 16;
            float g = gs[c], bb = bts[c];
            #pragma unroll
            for (int q4 = 0; q4 < 4; ++q4) {
                int p4 = p0 + q4 * 4;
                float4 xv = *(float4*)(ns + c * 136 + p4);
                float4 m4 = *(float4*)(mus + p4);
                float4 r4 = *(float4*)(rss + p4);
                if (c >= 10) {
                    float4 f4 = *(float4*)(invs + p4);
                    xv.x *= f4.x; xv.y *= f4.y; xv.z *= f4.z; xv.w *= f4.w;
                }
                float4 o4;
                o4.x = (xv.x - m4.x) * r4.x * g + bb;
                o4.y = (xv.y - m4.y) * r4.y * g + bb;
                o4.z = (xv.z - m4.z) * r4.z * g + bb;
                o4.w = (xv.w - m4.w) * r4.w * g + bb;
                *(float4*)(ob + (c * 128 + y) * 128 + p4) = o4;
            }
        }
        __syncthreads();
    }
}

extern "C" void kernel_launch(void* const* d_in, const int* in_sizes, int n_in,
                              void* d_out, int out_size)
{
    const float* x     = (const float*)d_in[0];
    const float* w1    = (const float*)d_in[1];
    const float* b1    = (const float*)d_in[2];
    const float* w2    = (const float*)d_in[3];
    const float* b2    = (const float*)d_in[4];
    const float* gamma = (const float*)d_in[5];
    const float* beta  = (const float*)d_in[6];
    float* out = (float*)d_out;

    cudaFuncSetAttribute(cellnn_kernel,
                         cudaFuncAttributeMaxDynamicSharedMemorySize, SM_TOTAL);

    cellnn_kernel<<<1024, THREADS, SM_TOTAL>>>(x, w1, b1, w2, b2, gamma, beta, out);
}

// round 12
// speedup vs baseline: 1.7676x; 1.0568x over previous
#include <cuda_runtime.h>
#include <cstdint>

#define THREADS 256
#define ROWS_PER_BLOCK 8

typedef unsigned long long ull;

// ---------------- SMEM layout (byte offsets) ----------------
#define SM_PERCP 0         // [56 kp][128 px] float2, SWZ1                 57344
#define SM_W1P   57344     // [56 kp][128 o ] float2, SWZ1                 57344
#define SM_HSP   114688    // [64 r ][128 px] float2, SWZ1 ^ KMASK(r)      65536
#define SM_W2P   180224    // [64 kp][32 c  ] float2                       16384
#define SM_NS    196608    // [32 c][136 px] float                         17408
#define SM_B1    214016
#define SM_B2    214528
#define SM_G     214656
#define SM_BETA  214784
#define SM_MU    214912
#define SM_RS    215424
#define SM_INV   215936
#define SM_TOTAL 216448

// swizzle within a 1024B row: byte bits 7-8 -> bank-group bits 4-5
#define SWZ1(o) ((uint32_t)(o) ^ ((((uint32_t)(o)) >> 3) & 0x30u))
// hsp row-dependent mask: r>>2 bits -> addr bits 4,5,8
#define KMASK(r) ((((((uint32_t)(r)) >> 2) & 3u) << 4) ^ (((((uint32_t)(r)) >> 2) & 4u) << 6))

#define BARG() asm volatile("bar.sync 1, 128;" ::: "memory")

__device__ __forceinline__ void ffma2(ull& d, ull a, ull b) {
    asm("fma.rn.f32x2 %0, %1, %2, %0;" : "+l"(d) : "l"(a), "l"(b));
}
__device__ __forceinline__ void unpack2(ull p, float& lo, float& hi) {
    asm("mov.b64 {%0, %1}, %2;" : "=f"(lo), "=f"(hi) : "l"(p));
}

// perceive value: channel k (0..111) at pixel (y, m)
__device__ __forceinline__ float perc_val(const float* __restrict__ xb, int y, int m, int k) {
    if (k < 32) return xb[(k * 128 + y) * 128 + m];
    int kk = k - 32;
    int c = kk >> 3, s = kk & 7;
    int idx = s + (s >= 4 ? 1 : 0);          // skip center tap
    int ki = idx / 3;
    int dy = ki - 1, dxx = idx - ki * 3 - 1;
    int yy = y + dy, xx = m + dxx;
    if ((unsigned)yy < 128u && (unsigned)xx < 128u)
        return xb[(c * 128 + yy) * 128 + xx];
    return 0.0f;
}

extern __shared__ char smem[];

__global__ void __launch_bounds__(THREADS, 1)
cellnn_kernel(const float* __restrict__ x,
              const float* __restrict__ w1,
              const float* __restrict__ b1,
              const float* __restrict__ w2,
              const float* __restrict__ b2,
              const float* __restrict__ gamma,
              const float* __restrict__ beta,
              float* __restrict__ out)
{
    float* b1s  = (float*)(smem + SM_B1);
    float* b2s  = (float*)(smem + SM_B2);
    float* gs   = (float*)(smem + SM_G);
    float* bts  = (float*)(smem + SM_BETA);
    float* mus  = (float*)(smem + SM_MU);
    float* rss  = (float*)(smem + SM_RS);
    float* invs = (float*)(smem + SM_INV);
    float* ns   = (float*)(smem + SM_NS);

    const int tid  = threadIdx.x;
    const int lane = tid & 31;
    const int warp = tid >> 5;

    // ---- stage w1p[kp][o] = (w1[o][2kp], w1[o][2kp+1]), SWZ1 on o-offset ----
    #pragma unroll
    for (int it = 0; it < 56; ++it) {
        int i = it * THREADS + tid;
        int k = i >> 7, o = i & 127;
        float v = w1[o * 112 + k];
        uint32_t a = (uint32_t)((k >> 1) * 1024) + SWZ1((uint32_t)(o * 8)) + (uint32_t)((k & 1) * 4);
        *(float*)(smem + SM_W1P + a) = v;
    }
    // ---- stage w2p[kp][c] = (w2[c][2kp], w2[c][2kp+1]) ----
    #pragma unroll
    for (int it = 0; it < 16; ++it) {
        int i = it * THREADS + tid;
        int k = i >> 5, c = i & 31;
        float v = w2[c * 128 + k];
        *(float*)(smem + SM_W2P + (k >> 1) * 256 + c * 8 + (k & 1) * 4) = v;
    }
    if (tid < 128) b1s[tid] = b1[tid];
    if (tid < 32) { b2s[tid] = b2[tid]; gs[tid] = gamma[tid]; bts[tid] = beta[tid]; }

    const int row0 = blockIdx.x * ROWS_PER_BLOCK;
    const int bi   = row0 >> 7;
    const int y0   = row0 & 127;
    const float* xb = x   + (size_t)bi * 32 * 128 * 128;
    float*       ob = out + (size_t)bi * 32 * 128 * 128;

    // ---- GEMM1 mapping: thread 8px x 8o; 8 warps cover 128x128
    const int g1_p0 = ((warp & 3) * 4 + (lane & 3)) * 8;
    const int g1_o0 = ((warp >> 2) * 8 + (lane >> 2)) * 8;
    uint32_t a_off[4], w_off[4];
    #pragma unroll
    for (int c = 0; c < 4; ++c) {
        a_off[c] = SWZ1((uint32_t)(g1_p0 * 8 + c * 16));
        w_off[c] = SWZ1((uint32_t)(g1_o0 * 8 + c * 16));
    }
    uint32_t h_off[4][4];
    #pragma unroll
    for (int jp = 0; jp < 4; ++jp) {
        uint32_t r = (uint32_t)(g1_o0 / 2 + jp);
        uint32_t km = KMASK(r);
        #pragma unroll
        for (int c = 0; c < 4; ++c)
            h_off[jp][c] = r * 1024 + (SWZ1((uint32_t)(g1_p0 * 8 + c * 16)) ^ km);
    }

    // ---- GEMM2 mapping (warps 0-3 only): thread 8px x 4c; 128 threads cover 128x32
    const int g2_p0 = ((warp & 3) * 4 + (lane & 3)) * 8;      // 8 px
    const int g2_c0 = (lane >> 2) * 4;                        // 4 c
    uint32_t g2_aoff[4];
    #pragma unroll
    for (int c = 0; c < 4; ++c)
        g2_aoff[c] = SWZ1((uint32_t)(g2_p0 * 8 + c * 16));

    // ---- prologue build: percp for row 0 (all 256 threads) ----
    #pragma unroll
    for (int it = 0; it < 28; ++it) {
        int i = it * THREADS + tid;
        int kp = i >> 7, px = i & 127;
        float v0 = perc_val(xb, y0, px, 2 * kp);
        float v1 = perc_val(xb, y0, px, 2 * kp + 1);
        uint32_t a = (uint32_t)(kp * 1024) + SWZ1((uint32_t)(px * 8));
        *(float2*)(smem + SM_PERCP + a) = make_float2(v0, v1);
    }
    __syncthreads();

    for (int r8 = 0; r8 < ROWS_PER_BLOCK; ++r8) {
        const int y = y0 + r8;

        // ================= GEMM1: all 8 warps =================
        {
            ull acc[64];
            #pragma unroll
            for (int i = 0; i < 64; ++i) acc[i] = 0ull;

            const char* pp = smem + SM_PERCP;
            const char* pw = smem + SM_W1P;
            #pragma unroll 2
            for (int kp = 0; kp < 56; ++kp) {
                uint32_t base = (uint32_t)kp << 10;
                ull Av[8], Wv[8];
                {
                    ulonglong2 t;
                    t = *(const ulonglong2*)(pp + base + a_off[0]); Av[0] = t.x; Av[1] = t.y;
                    t = *(const ulonglong2*)(pp + base + a_off[1]); Av[2] = t.x; Av[3] = t.y;
                    t = *(const ulonglong2*)(pp + base + a_off[2]); Av[4] = t.x; Av[5] = t.y;
                    t = *(const ulonglong2*)(pp + base + a_off[3]); Av[6] = t.x; Av[7] = t.y;
                    t = *(const ulonglong2*)(pw + base + w_off[0]); Wv[0] = t.x; Wv[1] = t.y;
                    t = *(const ulonglong2*)(pw + base + w_off[1]); Wv[2] = t.x; Wv[3] = t.y;
                    t = *(const ulonglong2*)(pw + base + w_off[2]); Wv[4] = t.x; Wv[5] = t.y;
                    t = *(const ulonglong2*)(pw + base + w_off[3]); Wv[6] = t.x; Wv[7] = t.y;
                }
                #pragma unroll
                for (int i = 0; i < 8; ++i)
                    #pragma unroll
                    for (int j = 0; j < 8; ++j)
                        ffma2(acc[i * 8 + j], Av[i], Wv[j]);
            }
            #pragma unroll
            for (int jp = 0; jp < 4; ++jp) {
                float be = b1s[g1_o0 + 2 * jp];
                float bo = b1s[g1_o0 + 2 * jp + 1];
                char* sb = smem + SM_HSP;
                #pragma unroll
                for (int c = 0; c < 4; ++c) {
                    float l, h;
                    float4 v;
                    unpack2(acc[(2 * c) * 8 + 2 * jp], l, h);
                    v.x = fmaxf(l + h + be, 0.0f);
                    unpack2(acc[(2 * c) * 8 + 2 * jp + 1], l, h);
                    v.y = fmaxf(l + h + bo, 0.0f);
                    unpack2(acc[(2 * c + 1) * 8 + 2 * jp], l, h);
                    v.z = fmaxf(l + h + be, 0.0f);
                    unpack2(acc[(2 * c + 1) * 8 + 2 * jp + 1], l, h);
                    v.w = fmaxf(l + h + bo, 0.0f);
                    *(float4*)(sb + h_off[jp][c]) = v;
                }
            }
        }
        __syncthreads();

        // ================= phase 2: warp-specialized =================
        if (warp < 4) {
            // ---- GEMM2: 8px x 4c; residual from global (L2-hot) ----
            float4 xres[4][2];
            #pragma unroll
            for (int j = 0; j < 4; ++j) {
                const float* xr = xb + ((g2_c0 + j) * 128 + y) * 128 + g2_p0;
                xres[j][0] = *(const float4*)(xr);
                xres[j][1] = *(const float4*)(xr + 4);
            }

            ull acc2[32];
            #pragma unroll
            for (int i = 0; i < 32; ++i) acc2[i] = 0ull;

            const char* ph = smem + SM_HSP;
            const char* pw = smem + SM_W2P + g2_c0 * 8;
            #pragma unroll 4
            for (int kp = 0; kp < 64; ++kp) {
                uint32_t km = KMASK(kp);
                uint32_t base = (uint32_t)(kp * 1024);
                ull Av[8], Wv[4];
                {
                    ulonglong2 t;
                    t = *(const ulonglong2*)(ph + base + (g2_aoff[0] ^ km)); Av[0] = t.x; Av[1] = t.y;
                    t = *(const ulonglong2*)(ph + base + (g2_aoff[1] ^ km)); Av[2] = t.x; Av[3] = t.y;
                    t = *(const ulonglong2*)(ph + base + (g2_aoff[2] ^ km)); Av[4] = t.x; Av[5] = t.y;
                    t = *(const ulonglong2*)(ph + base + (g2_aoff[3] ^ km)); Av[6] = t.x; Av[7] = t.y;
                    t = *(const ulonglong2*)(pw + kp * 256);      Wv[0] = t.x; Wv[1] = t.y;
                    t = *(const ulonglong2*)(pw + kp * 256 + 16); Wv[2] = t.x; Wv[3] = t.y;
                }
                #pragma unroll
                for (int j = 0; j < 4; ++j)
                    #pragma unroll
                    for (int i = 0; i < 8; ++i)
                        ffma2(acc2[j * 8 + i], Av[i], Wv[j]);
            }
            #pragma unroll
            for (int j = 0; j < 4; ++j) {
                int c = g2_c0 + j;
                float bj = b2s[c];
                float4 v0, v1;
                float lo, hi;
                unpack2(acc2[j * 8 + 0], lo, hi); v0.x = lo + hi + bj + xres[j][0].x;
                unpack2(acc2[j * 8 + 1], lo, hi); v0.y = lo + hi + bj + xres[j][0].y;
                unpack2(acc2[j * 8 + 2], lo, hi); v0.z = lo + hi + bj + xres[j][0].z;
                unpack2(acc2[j * 8 + 3], lo, hi); v0.w = lo + hi + bj + xres[j][0].w;
                unpack2(acc2[j * 8 + 4], lo, hi); v1.x = lo + hi + bj + xres[j][1].x;
                unpack2(acc2[j * 8 + 5], lo, hi); v1.y = lo + hi + bj + xres[j][1].y;
                unpack2(acc2[j * 8 + 6], lo, hi); v1.z = lo + hi + bj + xres[j][1].z;
                unpack2(acc2[j * 8 + 7], lo, hi); v1.w = lo + hi + bj + xres[j][1].w;
                *(float4*)(ns + c * 136 + g2_p0)     = v0;
                *(float4*)(ns + c * 136 + g2_p0 + 4) = v1;
            }
            BARG();

            // ---- stats: thread = pixel, all 32 channels ----
            {
                int p = tid;                    // 0..127
                const float* np = ns + p;
                float v0 = np[0];
                float best = v0;
                int arg = 0;
                float sv = v0, qv = v0 * v0;
                #pragma unroll
                for (int c = 1; c < 10; ++c) {
                    float v = np[c * 136];
                    sv += v; qv = fmaf(v, v, qv);
                    if (v > best) { best = v; arg = c; }
                }
                float sh = 0.0f, qh = 0.0f;
                #pragma unroll
                for (int c = 10; c < 32; ++c) {
                    float v = np[c * 136];
                    sh += v; qh = fmaf(v, v, qh);
                }
                float f = (arg != 0) ? 1.0f : 0.0f;
                float s = sv + f * sh;
                float q = qv + f * qh;
                float mu = s * (1.0f / 32.0f);
                float var = q * (1.0f / 32.0f) - mu * mu;
                mus[p]  = mu;
                rss[p]  = rsqrtf(var + 1e-5f);
                invs[p] = f;
            }
            BARG();

            // ---- normalize + store: thread = (c, px-quarter) ----
            {
                int c = tid >> 2, q = tid & 3;
                int pb = q * 32;
                float g = gs[c], bb = bts[c];
                #pragma unroll
                for (int q4 = 0; q4 < 8; ++q4) {
                    int p4 = pb + q4 * 4;
                    float4 xv = *(float4*)(ns + c * 136 + p4);
                    float4 m4 = *(float4*)(mus + p4);
                    float4 r4 = *(float4*)(rss + p4);
                    if (c >= 10) {
                        float4 f4 = *(float4*)(invs + p4);
                        xv.x *= f4.x; xv.y *= f4.y; xv.z *= f4.z; xv.w *= f4.w;
                    }
                    float4 o4;
                    o4.x = (xv.x - m4.x) * r4.x * g + bb;
                    o4.y = (xv.y - m4.y) * r4.y * g + bb;
                    o4.z = (xv.z - m4.z) * r4.z * g + bb;
                    o4.w = (xv.w - m4.w) * r4.w * g + bb;
                    *(float4*)(ob + (c * 128 + y) * 128 + p4) = o4;
                }
            }
        } else if (r8 + 1 < ROWS_PER_BLOCK) {
            // ---- build percp for row r8+1 (warps 4-7, 128 threads) ----
            const int yn = y + 1;
            const int tid2 = tid & 127;
            #pragma unroll
            for (int it = 0; it < 56; ++it) {
                int i = it * 128 + tid2;
                int kp = i >> 7, px = i & 127;
                float v0 = perc_val(xb, yn, px, 2 * kp);
                float v1 = perc_val(xb, yn, px, 2 * kp + 1);
                uint32_t a = (uint32_t)(kp * 1024) + SWZ1((uint32_t)(px * 8));
                *(float2*)(smem + SM_PERCP + a) = make_float2(v0, v1);
            }
        }
        __syncthreads();
    }
}

extern "C" void kernel_launch(void* const* d_in, const int* in_sizes, int n_in,
                              void* d_out, int out_size)
{
    const float* x     = (const float*)d_in[0];
    const float* w1    = (const float*)d_in[1];
    const float* b1    = (const float*)d_in[2];
    const float* w2    = (const float*)d_in[3];
    const float* b2    = (const float*)d_in[4];
    const float* gamma = (const float*)d_in[5];
    const float* beta  = (const float*)d_in[6];
    float* out = (float*)d_out;

    cudaFuncSetAttribute(cellnn_kernel,
                         cudaFuncAttributeMaxDynamicSharedMemorySize, SM_TOTAL);

    cellnn_kernel<<<1024, THREADS, SM_TOTAL>>>(x, w1, b1, w2, b2, gamma, beta, out);
}

// round 13
// speedup vs baseline: 1.8230x; 1.0314x over previous
#include <cuda_runtime.h>
#include <cstdint>

#define THREADS 256
#define ROWS_PER_BLOCK 8

typedef unsigned long long ull;

// ---------------- SMEM layout (byte offsets) ----------------
#define SM_PERCP 0         // [56 kp][128 px] float2, SWZ1                 57344
#define SM_W1P   57344     // [56 kp][128 o ] float2, SWZ1                 57344
#define SM_HSP   114688    // [64 r ][128 px] float2, SWZ1 ^ KMASK(r)      65536
#define SM_PART  (114688 + 32768)   // partial dx: [16][128] float2 (16KB, aliases hsp kp32-63 after use)
#define SM_W2P   180224    // [64 kp][32 c  ] float2                       16384
#define SM_NS    196608    // [32 c][136 px] float                         17408
#define SM_B1    214016
#define SM_B2    214528
#define SM_G     214656
#define SM_BETA  214784
#define SM_MU    214912
#define SM_RS    215424
#define SM_INV   215936
#define SM_TOTAL 216448

// swizzle within a 1024B row: byte bits 7-8 -> bank-group bits 4-5
#define SWZ1(o) ((uint32_t)(o) ^ ((((uint32_t)(o)) >> 3) & 0x30u))
// hsp row-dependent mask: r>>2 bits -> addr bits 4,5,8
#define KMASK(r) ((((((uint32_t)(r)) >> 2) & 3u) << 4) ^ (((((uint32_t)(r)) >> 2) & 4u) << 6))

#define BARG() asm volatile("bar.sync 1, 128;" ::: "memory")

__device__ __forceinline__ void ffma2(ull& d, ull a, ull b) {
    asm("fma.rn.f32x2 %0, %1, %2, %0;" : "+l"(d) : "l"(a), "l"(b));
}
__device__ __forceinline__ void unpack2(ull p, float& lo, float& hi) {
    asm("mov.b64 {%0, %1}, %2;" : "=f"(lo), "=f"(hi) : "l"(p));
}

// perceive value: channel k (0..111) at pixel (y, m)
__device__ __forceinline__ float perc_val(const float* __restrict__ xb, int y, int m, int k) {
    if (k < 32) return xb[(k * 128 + y) * 128 + m];
    int kk = k - 32;
    int c = kk >> 3, s = kk & 7;
    int idx = s + (s >= 4 ? 1 : 0);          // skip center tap
    int ki = idx / 3;
    int dy = ki - 1, dxx = idx - ki * 3 - 1;
    int yy = y + dy, xx = m + dxx;
    if ((unsigned)yy < 128u && (unsigned)xx < 128u)
        return xb[(c * 128 + yy) * 128 + xx];
    return 0.0f;
}

extern __shared__ char smem[];

__global__ void __launch_bounds__(THREADS, 1)
cellnn_kernel(const float* __restrict__ x,
              const float* __restrict__ w1,
              const float* __restrict__ b1,
              const float* __restrict__ w2,
              const float* __restrict__ b2,
              const float* __restrict__ gamma,
              const float* __restrict__ beta,
              float* __restrict__ out)
{
    float* b1s  = (float*)(smem + SM_B1);
    float* b2s  = (float*)(smem + SM_B2);
    float* gs   = (float*)(smem + SM_G);
    float* bts  = (float*)(smem + SM_BETA);
    float* mus  = (float*)(smem + SM_MU);
    float* rss  = (float*)(smem + SM_RS);
    float* invs = (float*)(smem + SM_INV);
    float* ns   = (float*)(smem + SM_NS);

    const int tid  = threadIdx.x;
    const int lane = tid & 31;
    const int warp = tid >> 5;

    // ---- stage w1p[kp][o] = (w1[o][2kp], w1[o][2kp+1]), SWZ1 on o-offset ----
    #pragma unroll
    for (int it = 0; it < 56; ++it) {
        int i = it * THREADS + tid;
        int k = i >> 7, o = i & 127;
        float v = w1[o * 112 + k];
        uint32_t a = (uint32_t)((k >> 1) * 1024) + SWZ1((uint32_t)(o * 8)) + (uint32_t)((k & 1) * 4);
        *(float*)(smem + SM_W1P + a) = v;
    }
    // ---- stage w2p[kp][c] = (w2[c][2kp], w2[c][2kp+1]) ----
    #pragma unroll
    for (int it = 0; it < 16; ++it) {
        int i = it * THREADS + tid;
        int k = i >> 5, c = i & 31;
        float v = w2[c * 128 + k];
        *(float*)(smem + SM_W2P + (k >> 1) * 256 + c * 8 + (k & 1) * 4) = v;
    }
    if (tid < 128) b1s[tid] = b1[tid];
    if (tid < 32) { b2s[tid] = b2[tid]; gs[tid] = gamma[tid]; bts[tid] = beta[tid]; }

    const int row0 = blockIdx.x * ROWS_PER_BLOCK;
    const int bi   = row0 >> 7;
    const int y0   = row0 & 127;
    const float* xb = x   + (size_t)bi * 32 * 128 * 128;
    float*       ob = out + (size_t)bi * 32 * 128 * 128;

    // ---- GEMM1 mapping: thread 8px x 8o; 8 warps cover 128x128
    const int g1_p0 = ((warp & 3) * 4 + (lane & 3)) * 8;
    const int g1_o0 = ((warp >> 2) * 8 + (lane >> 2)) * 8;
    uint32_t a_off[4], w_off[4];
    #pragma unroll
    for (int c = 0; c < 4; ++c) {
        a_off[c] = SWZ1((uint32_t)(g1_p0 * 8 + c * 16));
        w_off[c] = SWZ1((uint32_t)(g1_o0 * 8 + c * 16));
    }
    uint32_t h_off[4][4];
    #pragma unroll
    for (int jp = 0; jp < 4; ++jp) {
        uint32_t r = (uint32_t)(g1_o0 / 2 + jp);
        uint32_t km = KMASK(r);
        #pragma unroll
        for (int c = 0; c < 4; ++c)
            h_off[jp][c] = r * 1024 + (SWZ1((uint32_t)(g1_p0 * 8 + c * 16)) ^ km);
    }

    // ---- GEMM2 mapping (split-K): all warps, thread 8px x 4c; warp>>2 = kp half
    const int g2_hh = warp >> 2;                              // 0: kp 0-31, 1: kp 32-63
    const int g2_p0 = ((warp & 3) * 4 + (lane & 3)) * 8;      // 8 px
    const int g2_c0 = (lane >> 2) * 4;                        // 4 c
    uint32_t g2_aoff[4];
    #pragma unroll
    for (int c = 0; c < 4; ++c)
        g2_aoff[c] = SWZ1((uint32_t)(g2_p0 * 8 + c * 16));

    // ---- prologue build: percp for row 0 (all 256 threads) ----
    #pragma unroll
    for (int it = 0; it < 28; ++it) {
        int i = it * THREADS + tid;
        int kp = i >> 7, px = i & 127;
        float v0 = perc_val(xb, y0, px, 2 * kp);
        float v1 = perc_val(xb, y0, px, 2 * kp + 1);
        uint32_t a = (uint32_t)(kp * 1024) + SWZ1((uint32_t)(px * 8));
        *(float2*)(smem + SM_PERCP + a) = make_float2(v0, v1);
    }
    __syncthreads();

    for (int r8 = 0; r8 < ROWS_PER_BLOCK; ++r8) {
        const int y = y0 + r8;

        // ================= GEMM1: all 8 warps =================
        {
            ull acc[64];
            #pragma unroll
            for (int i = 0; i < 64; ++i) acc[i] = 0ull;

            const char* pp = smem + SM_PERCP;
            const char* pw = smem + SM_W1P;
            #pragma unroll 2
            for (int kp = 0; kp < 56; ++kp) {
                uint32_t base = (uint32_t)kp << 10;
                ull Av[8], Wv[8];
                {
                    ulonglong2 t;
                    t = *(const ulonglong2*)(pp + base + a_off[0]); Av[0] = t.x; Av[1] = t.y;
                    t = *(const ulonglong2*)(pp + base + a_off[1]); Av[2] = t.x; Av[3] = t.y;
                    t = *(const ulonglong2*)(pp + base + a_off[2]); Av[4] = t.x; Av[5] = t.y;
                    t = *(const ulonglong2*)(pp + base + a_off[3]); Av[6] = t.x; Av[7] = t.y;
                    t = *(const ulonglong2*)(pw + base + w_off[0]); Wv[0] = t.x; Wv[1] = t.y;
                    t = *(const ulonglong2*)(pw + base + w_off[1]); Wv[2] = t.x; Wv[3] = t.y;
                    t = *(const ulonglong2*)(pw + base + w_off[2]); Wv[4] = t.x; Wv[5] = t.y;
                    t = *(const ulonglong2*)(pw + base + w_off[3]); Wv[6] = t.x; Wv[7] = t.y;
                }
                #pragma unroll
                for (int i = 0; i < 8; ++i)
                    #pragma unroll
                    for (int j = 0; j < 8; ++j)
                        ffma2(acc[i * 8 + j], Av[i], Wv[j]);
            }
            #pragma unroll
            for (int jp = 0; jp < 4; ++jp) {
                float be = b1s[g1_o0 + 2 * jp];
                float bo = b1s[g1_o0 + 2 * jp + 1];
                char* sb = smem + SM_HSP;
                #pragma unroll
                for (int c = 0; c < 4; ++c) {
                    float l, h;
                    float4 v;
                    unpack2(acc[(2 * c) * 8 + 2 * jp], l, h);
                    v.x = fmaxf(l + h + be, 0.0f);
                    unpack2(acc[(2 * c) * 8 + 2 * jp + 1], l, h);
                    v.y = fmaxf(l + h + bo, 0.0f);
                    unpack2(acc[(2 * c + 1) * 8 + 2 * jp], l, h);
                    v.z = fmaxf(l + h + be, 0.0f);
                    unpack2(acc[(2 * c + 1) * 8 + 2 * jp + 1], l, h);
                    v.w = fmaxf(l + h + bo, 0.0f);
                    *(float4*)(sb + h_off[jp][c]) = v;
                }
            }
        }
        __syncthreads();

        // ================= GEMM2 split-K: all 8 warps, half kp range each =========
        ull acc2[32];
        #pragma unroll
        for (int i = 0; i < 32; ++i) acc2[i] = 0ull;
        {
            const char* ph = smem + SM_HSP;
            const char* pw = smem + SM_W2P + g2_c0 * 8;
            const int kp0 = g2_hh * 32;
            #pragma unroll 4
            for (int kq = 0; kq < 32; ++kq) {
                int kp = kp0 + kq;
                uint32_t km = KMASK(kp);
                uint32_t base = (uint32_t)(kp * 1024);
                ull Av[8], Wv[4];
                {
                    ulonglong2 t;
                    t = *(const ulonglong2*)(ph + base + (g2_aoff[0] ^ km)); Av[0] = t.x; Av[1] = t.y;
                    t = *(const ulonglong2*)(ph + base + (g2_aoff[1] ^ km)); Av[2] = t.x; Av[3] = t.y;
                    t = *(const ulonglong2*)(ph + base + (g2_aoff[2] ^ km)); Av[4] = t.x; Av[5] = t.y;
                    t = *(const ulonglong2*)(ph + base + (g2_aoff[3] ^ km)); Av[6] = t.x; Av[7] = t.y;
                    t = *(const ulonglong2*)(pw + kp * 256);      Wv[0] = t.x; Wv[1] = t.y;
                    t = *(const ulonglong2*)(pw + kp * 256 + 16); Wv[2] = t.x; Wv[3] = t.y;
                }
                #pragma unroll
                for (int j = 0; j < 4; ++j)
                    #pragma unroll
                    for (int i = 0; i < 8; ++i)
                        ffma2(acc2[j * 8 + i], Av[i], Wv[j]);
            }
        }

        float4 xres[4][2];
        if (warp < 4) {
            // prefetch residual from global (L2-hot) while group 1 stores partials
            #pragma unroll
            for (int j = 0; j < 4; ++j) {
                const float* xr = xb + ((g2_c0 + j) * 128 + y) * 128 + g2_p0;
                xres[j][0] = *(const float4*)(xr);
                xres[j][1] = *(const float4*)(xr + 4);
            }
        } else {
            // group 1: collapse f32x2 pairs, store partials (own hsp half is dead now)
            const int tid2 = tid - 128;
            char* pb = smem + SM_PART + tid2 * 8;
            #pragma unroll
            for (int j = 0; j < 4; ++j) {
                #pragma unroll
                for (int ii = 0; ii < 4; ++ii) {
                    float l0, h0, l1, h1;
                    unpack2(acc2[j * 8 + 2 * ii], l0, h0);
                    unpack2(acc2[j * 8 + 2 * ii + 1], l1, h1);
                    *(float2*)(pb + (j * 4 + ii) * 1024) = make_float2(l0 + h0, l1 + h1);
                }
            }
        }
        __syncthreads();

        // ================= phase 3: warp-specialized =================
        if (warp < 4) {
            // ---- reduce partials + residual -> ns ----
            const char* pb = smem + SM_PART + tid * 8;
            #pragma unroll
            for (int j = 0; j < 4; ++j) {
                int c = g2_c0 + j;
                float bj = b2s[c];
                float4 v0, v1;
                float l, h;
                float2 p0 = *(const float2*)(pb + (j * 4 + 0) * 1024);
                float2 p1 = *(const float2*)(pb + (j * 4 + 1) * 1024);
                float2 p2 = *(const float2*)(pb + (j * 4 + 2) * 1024);
                float2 p3 = *(const float2*)(pb + (j * 4 + 3) * 1024);
                unpack2(acc2[j * 8 + 0], l, h); v0.x = l + h + p0.x + bj + xres[j][0].x;
                unpack2(acc2[j * 8 + 1], l, h); v0.y = l + h + p0.y + bj + xres[j][0].y;
                unpack2(acc2[j * 8 + 2], l, h); v0.z = l + h + p1.x + bj + xres[j][0].z;
                unpack2(acc2[j * 8 + 3], l, h); v0.w = l + h + p1.y + bj + xres[j][0].w;
                unpack2(acc2[j * 8 + 4], l, h); v1.x = l + h + p2.x + bj + xres[j][1].x;
                unpack2(acc2[j * 8 + 5], l, h); v1.y = l + h + p2.y + bj + xres[j][1].y;
                unpack2(acc2[j * 8 + 6], l, h); v1.z = l + h + p3.x + bj + xres[j][1].z;
                unpack2(acc2[j * 8 + 7], l, h); v1.w = l + h + p3.y + bj + xres[j][1].w;
                *(float4*)(ns + c * 136 + g2_p0)     = v0;
                *(float4*)(ns + c * 136 + g2_p0 + 4) = v1;
            }
            BARG();

            // ---- stats: thread = pixel, all 32 channels ----
            {
                int p = tid;
                const float* np = ns + p;
                float v0 = np[0];
                float best = v0;
                int arg = 0;
                float sv = v0, qv = v0 * v0;
                #pragma unroll
                for (int c = 1; c < 10; ++c) {
                    float v = np[c * 136];
                    sv += v; qv = fmaf(v, v, qv);
                    if (v > best) { best = v; arg = c; }
                }
                float sh = 0.0f, qh = 0.0f;
                #pragma unroll
                for (int c = 10; c < 32; ++c) {
                    float v = np[c * 136];
                    sh += v; qh = fmaf(v, v, qh);
                }
                float f = (arg != 0) ? 1.0f : 0.0f;
                float s = sv + f * sh;
                float q = qv + f * qh;
                float mu = s * (1.0f / 32.0f);
                float var = q * (1.0f / 32.0f) - mu * mu;
                mus[p]  = mu;
                rss[p]  = rsqrtf(var + 1e-5f);
                invs[p] = f;
            }
            BARG();

            // ---- normalize + store ----
            {
                int c = tid >> 2, q = tid & 3;
                int pbx = q * 32;
                float g = gs[c], bb = bts[c];
                #pragma unroll
                for (int q4 = 0; q4 < 8; ++q4) {
                    int p4 = pbx + q4 * 4;
                    float4 xv = *(float4*)(ns + c * 136 + p4);
                    float4 m4 = *(float4*)(mus + p4);
                    float4 r4 = *(float4*)(rss + p4);
                    if (c >= 10) {
                        float4 f4 = *(float4*)(invs + p4);
                        xv.x *= f4.x; xv.y *= f4.y; xv.z *= f4.z; xv.w *= f4.w;
                    }
                    float4 o4;
                    o4.x = (xv.x - m4.x) * r4.x * g + bb;
                    o4.y = (xv.y - m4.y) * r4.y * g + bb;
                    o4.z = (xv.z - m4.z) * r4.z * g + bb;
                    o4.w = (xv.w - m4.w) * r4.w * g + bb;
                    *(float4*)(ob + (c * 128 + y) * 128 + p4) = o4;
                }
            }
        } else if (r8 + 1 < ROWS_PER_BLOCK) {
            // ---- build percp for row r8+1 (warps 4-7) ----
            const int yn = y + 1;
            const int tid2 = tid & 127;
            #pragma unroll
            for (int it = 0; it < 56; ++it) {
                int i = it * 128 + tid2;
                int kp = i >> 7, px = i & 127;
                float v0 = perc_val(xb, yn, px, 2 * kp);
                float v1 = perc_val(xb, yn, px, 2 * kp + 1);
                uint32_t a = (uint32_t)(kp * 1024) + SWZ1((uint32_t)(px * 8));
                *(float2*)(smem + SM_PERCP + a) = make_float2(v0, v1);
            }
        }
        __syncthreads();
    }
}

extern "C" void kernel_launch(void* const* d_in, const int* in_sizes, int n_in,
                              void* d_out, int out_size)
{
    const float* x     = (const float*)d_in[0];
    const float* w1    = (const float*)d_in[1];
    const float* b1    = (const float*)d_in[2];
    const float* w2    = (const float*)d_in[3];
    const float* b2    = (const float*)d_in[4];
    const float* gamma = (const float*)d_in[5];
    const float* beta  = (const float*)d_in[6];
    float* out = (float*)d_out;

    cudaFuncSetAttribute(cellnn_kernel,
                         cudaFuncAttributeMaxDynamicSharedMemorySize, SM_TOTAL);

    cellnn_kernel<<<1024, THREADS, SM_TOTAL>>>(x, w1, b1, w2, b2, gamma, beta, out);
}